// round 17
// baseline (speedup 1.0000x reference)
#include <cuda_runtime.h>
#include <cstdint>

#define NC  5
#define TPB 256
#define NBLK 444    // 3 CTAs on each of 148 SMs, uniform residency

__device__ __forceinline__ float fast_ex2(float x) {
    float y; asm("ex2.approx.f32 %0, %1;" : "=f"(y) : "f"(x)); return y;
}
__device__ __forceinline__ float fast_lg2(float x) {
    float y; asm("lg2.approx.f32 %0, %1;" : "=f"(y) : "f"(x)); return y;
}
__device__ __forceinline__ float fast_rcp(float x) {
    float y; asm("rcp.approx.f32 %0, %1;" : "=f"(y) : "f"(x)); return y;
}
__device__ __forceinline__ float fast_rsq(float x) {
    float y; asm("rsqrt.approx.f32 %0, %1;" : "=f"(y) : "f"(x)); return y;
}

// h(t) = t*mu(t) - log2 Z(t) + C2 (log2 domain), C2=(ln5-eps)/ln2, increasing.
// p(t) = softmax(t * log2 q). Feasible (lam=0) iff h(1) <= 0, then p = q/sum(q).
#define C2CONST 2.1776498f     // (ln5 - 0.1)/ln2
#define LN2SQ   0.48045302f    // ln2^2
#define LN2CU   0.33302465f    // ln2^3
#define RLN2    1.44269504f    // 1/ln2
#define SQ2EPS  0.44721360f    // sqrt(2*eps)

// Solve h(t)=0 on (0,1): cubic-Taylor init + 3 safeguarded Newton steps.
__device__ __forceinline__ float solve_row(const float L[NC]) {
    float s1 = 0.f, s2 = 0.f, s3 = 0.f;
    #pragma unroll
    for (int j = 0; j < NC; j++) {
        float lj = L[j];
        s1 += lj; s2 = fmaf(lj, lj, s2); s3 = fmaf(lj * lj, lj, s3);
    }
    float m   = s1 * 0.2f;
    float e2  = s2 * 0.2f;
    float V   = fmaxf(LN2SQ * (e2 - m * m), 1e-9f);
    float m3  = LN2CU * fmaf(s3, 0.2f, fmaf(-3.f * m, e2, 2.f * m * m * m));
    float tl  = SQ2EPS * fast_rsq(V);
    float den = fmaxf(fmaf(0.6666667f * m3, tl, V), 1e-9f);
    float tc  = fminf(0.95f, fmaxf(SQ2EPS * fast_rsq(den), 1e-4f));

    float lo = 0.f, hi = 1.f;
    #pragma unroll
    for (int it = 0; it < 3; ++it) {
        float S = 0.f, A = 0.f, B = 0.f;
        #pragma unroll
        for (int j = 0; j < NC; j++) {
            float e  = fast_ex2(tc * L[j]);
            float el = e * L[j];
            S += e; A = fmaf(e, L[j], A); B = fmaf(el, L[j], B);
        }
        float r  = fast_rcp(S);
        float mu = A * r;
        float v  = fmaf(B, r, -(mu * mu));
        float h  = fmaf(tc, mu, C2CONST - fast_lg2(S));
        float hp = tc * v;
        bool pos = (h > 0.f);
        hi = pos ? tc : hi;
        lo = pos ? lo : tc;
        float tn = fmaf(-h * RLN2, fast_rcp(hp), tc);
        bool ok = (tn > lo) && (tn < hi);   // false also on NaN
        tc = ok ? tn : 0.5f * (lo + hi);
    }
    return tc;
}

// Process one row held in a[0..4] (q overwrites in place), return 1/sum.
__device__ __forceinline__ float do_row(float* a, const float* sW, const float* sb) {
    float q[NC];
    float s = 0.f, A = 0.f;
    #pragma unroll
    for (int j = 0; j < NC; j++) {
        float qq = sb[j];
        #pragma unroll
        for (int k = 0; k < NC; k++) qq = fmaf(a[k], sW[j * NC + k], qq);
        q[j] = qq;
        s += qq;
        A = fmaf(qq, fast_lg2(qq), A);      // lg2 transient
    }
    float ir = fast_rcp(s);
    float h1 = A * ir - fast_lg2(s) + C2CONST;
    if (h1 > 0.f) {                          // infeasible: ~1% of rows
        float L[NC];
        #pragma unroll
        for (int j = 0; j < NC; j++) L[j] = fast_lg2(q[j]);
        float t = solve_row(L);
        float S = 0.f;
        #pragma unroll
        for (int j = 0; j < NC; j++) { q[j] = fast_ex2(t * L[j]); S += q[j]; }
        ir = fast_rcp(S);
    }
    #pragma unroll
    for (int j = 0; j < NC; j++) a[j] = q[j];
    return ir;
}

// ---- Persistent vec4 kernel: 4 rows/group, prefetch distance 1 ----
__global__ void __launch_bounds__(TPB) kl_proj_vec4p(
    const float4* __restrict__ x4,
    const float*  __restrict__ W,
    const float*  __restrict__ b,
    float4* __restrict__ o4,
    int ngroups)
{
    __shared__ float sW[NC * NC];
    __shared__ float sb[NC];
    if (threadIdx.x < NC * NC) sW[threadIdx.x] = W[threadIdx.x];
    if (threadIdx.x < NC)      sb[threadIdx.x] = b[threadIdx.x];
    __syncthreads();

    const int stride = gridDim.x * blockDim.x;
    int g = blockIdx.x * blockDim.x + threadIdx.x;

    float cur[20];
    bool have = (g < ngroups);
    if (have) {
        const float4* xin = x4 + (size_t)g * 5;
        #pragma unroll
        for (int i = 0; i < 5; i++) {
            float4 v = xin[i];
            cur[4*i] = v.x; cur[4*i+1] = v.y; cur[4*i+2] = v.z; cur[4*i+3] = v.w;
        }
    }

    while (have) {
        // ---- Prefetch next group (overlaps compute below) ----
        int  ng = g + stride;
        bool hn = (ng < ngroups);
        float nxt[20];
        if (hn) {
            const float4* xin = x4 + (size_t)ng * 5;
            #pragma unroll
            for (int i = 0; i < 5; i++) {
                float4 v = xin[i];
                nxt[4*i] = v.x; nxt[4*i+1] = v.y; nxt[4*i+2] = v.z; nxt[4*i+3] = v.w;
            }
        }

        // ---- Compute 4 rows in place ----
        float inv0 = do_row(cur +  0, sW, sb);
        float inv1 = do_row(cur +  5, sW, sb);
        float inv2 = do_row(cur + 10, sW, sb);
        float inv3 = do_row(cur + 15, sW, sb);
        #pragma unroll
        for (int j = 0; j < NC; j++) {
            cur[j]      *= inv0;
            cur[5 + j]  *= inv1;
            cur[10 + j] *= inv2;
            cur[15 + j] *= inv3;
        }

        // ---- Vec4 store ----
        float4* oo = o4 + (size_t)g * 5;
        #pragma unroll
        for (int i = 0; i < 5; i++)
            oo[i] = make_float4(cur[4*i], cur[4*i+1], cur[4*i+2], cur[4*i+3]);

        // ---- Rotate ----
        g = ng;
        have = hn;
        #pragma unroll
        for (int i = 0; i < 20; i++) cur[i] = nxt[i];
    }
}

// ---- Scalar persistent fallback (R15 winner): prefetch distance 1 ----
__global__ void __launch_bounds__(TPB) kl_proj_persist(
    const float* __restrict__ x,
    const float* __restrict__ W,
    const float* __restrict__ b,
    float* __restrict__ out,
    int n)
{
    __shared__ float sW[NC * NC];
    __shared__ float sb[NC];
    if (threadIdx.x < NC * NC) sW[threadIdx.x] = W[threadIdx.x];
    if (threadIdx.x < NC)      sb[threadIdx.x] = b[threadIdx.x];
    __syncthreads();

    const int stride = gridDim.x * blockDim.x;
    int row = blockIdx.x * blockDim.x + threadIdx.x;

    float cur[NC];
    bool have = (row < n);
    if (have) {
        #pragma unroll
        for (int k = 0; k < NC; k++) cur[k] = x[(size_t)row * NC + k];
    }

    while (have) {
        int  nrow  = row + stride;
        bool hnext = (nrow < n);
        float nxt[NC];
        if (hnext) {
            #pragma unroll
            for (int k = 0; k < NC; k++) nxt[k] = x[(size_t)nrow * NC + k];
        }

        float ir = do_row(cur, sW, sb);
        #pragma unroll
        for (int j = 0; j < NC; j++) out[(size_t)row * NC + j] = cur[j] * ir;

        row = nrow;
        have = hnext;
        #pragma unroll
        for (int k = 0; k < NC; k++) cur[k] = nxt[k];
    }
}

extern "C" void kernel_launch(void* const* d_in, const int* in_sizes, int n_in,
                              void* d_out, int out_size) {
    const float* x = (const float*)d_in[0];
    const float* W = (const float*)d_in[1];
    const float* b = (const float*)d_in[2];
    float* out = (float*)d_out;
    int n = in_sizes[0] / NC;   // 2,097,152 rows

    bool aligned = ((((uintptr_t)x) | ((uintptr_t)out)) & 15u) == 0 && (n % 4) == 0;
    if (aligned) {
        kl_proj_vec4p<<<NBLK, TPB>>>((const float4*)x, W, b, (float4*)out, n / 4);
    } else {
        kl_proj_persist<<<1024, TPB>>>(x, W, b, out, n);
    }
}